// round 8
// baseline (speedup 1.0000x reference)
#include <cuda_runtime.h>
#include <math.h>
#include <stdint.h>

#define N_PAT 4096
#define DIM   256
#define EPSV  1e-8f
#define RBLK  32                  // rows per prep block
#define NRB   (N_PAT / RBLK)      // 128 row-blocks per modality
#define NPREP (4 * NRB)           // 512 prep blocks
#define NCOXB 128                 // cox blocks, 32 rows each

// ---------------- static scratch ----------------
__device__ float  g_upart[NPREP * DIM];   // [prep block][col] -- coalesced both ways
__device__ float2 g_vw[NPREP];            // per (mod,rowblock) (V,W)
__device__ float  g_coxpart[N_PAT];

// ---------------- kernel 1: prep blocks + cox blocks in one grid ----------------
__global__ void __launch_bounds__(256)
main_kernel(const float* __restrict__ h, const int* __restrict__ t,
            const int* __restrict__ e,
            const float* __restrict__ eb0, const float* __restrict__ eb1,
            const float* __restrict__ eb2, const float* __restrict__ eb3) {
    __shared__ float smf[2048];     // prep: [8 warps][256 cols] | cox: exph tile (first 1024)
    __shared__ int   smi[1024];     // cox: t tile
    __shared__ float snm[8], sww[8];

    int tid = threadIdx.x;

    if (blockIdx.x < NPREP) {
        // ================= prep =================
        int mod = blockIdx.x >> 7;
        int rb  = blockIdx.x & 127;
        int r0  = rb * RBLK;
        const float* base = (mod == 0) ? eb0 : (mod == 1) ? eb1
                          : (mod == 2) ? eb2 : eb3;
        int w = tid >> 5, lane = tid & 31;

        // 4 rows per warp, all 8 float4 loads independent (MLP = 8)
        float4 va[4], vb[4];
#pragma unroll
        for (int rr = 0; rr < 4; rr++) {
            const float4* src = (const float4*)(base + (size_t)(r0 + w * 4 + rr) * DIM);
            va[rr] = src[lane];
            vb[rr] = src[lane + 32];
        }

        float4 acc0 = make_float4(0.f, 0.f, 0.f, 0.f);
        float4 acc1 = make_float4(0.f, 0.f, 0.f, 0.f);
        float nmW = 0.0f, wW = 0.0f;
#pragma unroll
        for (int rr = 0; rr < 4; rr++) {
            float4 v0 = va[rr], v1 = vb[rr];
            float x0 = __shfl_sync(0xffffffffu, v0.x, 0);
            bool eq = (v0.x == x0) && (v0.y == x0) && (v0.z == x0) && (v0.w == x0) &&
                      (v1.x == x0) && (v1.y == x0) && (v1.z == x0) && (v1.w == x0);
            bool miss = (__ballot_sync(0xffffffffu, eq) == 0xffffffffu);

            float ss = v0.x*v0.x + v0.y*v0.y + v0.z*v0.z + v0.w*v0.w
                     + v1.x*v1.x + v1.y*v1.y + v1.z*v1.z + v1.w*v1.w;
#pragma unroll
            for (int o = 16; o > 0; o >>= 1) ss += __shfl_xor_sync(0xffffffffu, ss, o);

            float den = fmaxf(sqrtf(ss), EPSV);
            float inv = miss ? 0.0f : (1.0f / den);
            if (!miss) { nmW += 1.0f; wW += ss / (den * den); }

            acc0.x += v0.x * inv; acc0.y += v0.y * inv;
            acc0.z += v0.z * inv; acc0.w += v0.w * inv;
            acc1.x += v1.x * inv; acc1.y += v1.y * inv;
            acc1.z += v1.z * inv; acc1.w += v1.w * inv;
        }

        float* row = smf + w * 256;
        *(float4*)(row + lane * 4)       = acc0;
        *(float4*)(row + 128 + lane * 4) = acc1;
        if (lane == 0) { snm[w] = nmW; sww[w] = wW; }
        __syncthreads();

        // cross-warp column sum; coalesced write (warp = 128B contiguous)
        float u = 0.0f;
#pragma unroll
        for (int ww = 0; ww < 8; ww++) u += smf[ww * 256 + tid];
        g_upart[((size_t)blockIdx.x << 8) + tid] = u;

        if (tid == 0) {
            float V = 0.0f, W = 0.0f;
#pragma unroll
            for (int i = 0; i < 8; i++) { V += snm[i]; W += sww[i]; }
            g_vw[blockIdx.x] = make_float2(V, W);
        }
    } else {
        // ================= cox: 32 rows per block =================
        int cb = blockIdx.x - NPREP;
        int il = tid >> 3;        // 0..31 local row
        int sub = tid & 7;
        int i = cb * 32 + il;
        int ti = t[i];
        float s = 0.0f;
        for (int j0 = 0; j0 < N_PAT; j0 += 1024) {
            __syncthreads();
            for (int j = tid; j < 1024; j += 256) {
                smi[j] = t[j0 + j];
                smf[j] = expf(h[j0 + j]);
            }
            __syncthreads();
#pragma unroll 8
            for (int j = sub; j < 1024; j += 8)
                if (ti == 0 || smi[j] >= ti) s += smf[j];
        }
#pragma unroll
        for (int o = 4; o > 0; o >>= 1) s += __shfl_xor_sync(0xffffffffu, s, o);
        if (sub == 0)
            g_coxpart[i] = e[i] ? (h[i] - logf(s)) : 0.0f;
    }
}

// ---------------- kernel 2: finish (coalesced, fully parallel) ----------------
__global__ void __launch_bounds__(1024)
finish_kernel(const int* __restrict__ e, const int* __restrict__ mptr,
              float* __restrict__ out) {
    __shared__ float rv[1024];
    __shared__ float rw[1024];
    __shared__ float U2s[4], sV[4], sW[4];
    int tid = threadIdx.x;

    // 1) per-mod ||u||^2 : thread = (mod,col); per rb step a warp reads 128B contiguous
    {
        int mod = tid >> 8, col = tid & 255;
        const float* up = g_upart + (((size_t)mod << 7) << 8) + col;
        float u = 0.0f;
#pragma unroll 16
        for (int rb = 0; rb < NRB; rb++) u += up[(size_t)rb << 8];
        rv[tid] = u * u;
    }
    __syncthreads();
#pragma unroll
    for (int o = 128; o > 0; o >>= 1) {
        if ((tid & 255) < o) rv[tid] += rv[tid + o];
        __syncthreads();
    }
    if (tid < 4) U2s[tid] = rv[tid << 8];
    __syncthreads();

    // 2) per-mod V, W (512 entries, 128 per mod)
    {
        float V = 0.0f, W = 0.0f;
        if (tid < NPREP) { float2 vw = g_vw[tid]; V = vw.x; W = vw.y; }
        rv[tid] = V; rw[tid] = W;
    }
    __syncthreads();
#pragma unroll
    for (int o = NRB / 2; o > 0; o >>= 1) {
        if (tid < NPREP && (tid & (NRB - 1)) < o) {
            rv[tid] += rv[tid + o];
            rw[tid] += rw[tid + o];
        }
        __syncthreads();
    }
    if (tid < 4) { sV[tid] = rv[tid * NRB]; sW[tid] = rw[tid * NRB]; }
    __syncthreads();

    // 3) cox partial sum + event count
    {
        float cp = 0.0f, ef = 0.0f;
#pragma unroll
        for (int k = 0; k < N_PAT / 1024; k++) {
            int i = tid + k * 1024;
            cp += g_coxpart[i];
            ef += (float)e[i];
        }
        rv[tid] = cp; rw[tid] = ef;
    }
    __syncthreads();
#pragma unroll
    for (int o = 512; o > 0; o >>= 1) {
        if (tid < o) { rv[tid] += rv[tid + o]; rw[tid] += rw[tid + o]; }
        __syncthreads();
    }

    if (tid == 0) {
        int iv = mptr[0];
        float margin = (iv > -1000000 && iv < 1000000) ? (float)iv : __int_as_float(iv);

        double sim = (double)margin * (double)N_PAT * (double)(N_PAT - 1);
#pragma unroll
        for (int m = 0; m < 4; m++)
            sim += (double)sW[m] * (double)sV[m] - (double)U2s[m];
        double cox = -(double)rv[0] / (double)rw[0];
        out[0] = (float)(sim + cox);
    }
}

// ---------------- launch ----------------
extern "C" void kernel_launch(void* const* d_in, const int* in_sizes, int n_in,
                              void* d_out, int out_size) {
    const float* h   = (const float*)d_in[0];
    const int*   t   = (const int*)d_in[1];
    const int*   e   = (const int*)d_in[2];
    const float* eb0 = (const float*)d_in[3];
    const float* eb1 = (const float*)d_in[4];
    const float* eb2 = (const float*)d_in[5];
    const float* eb3 = (const float*)d_in[6];
    const int*   mg  = (const int*)d_in[7];
    float* out = (float*)d_out;

    main_kernel<<<NPREP + NCOXB, 256>>>(h, t, e, eb0, eb1, eb2, eb3);
    finish_kernel<<<1, 1024>>>(e, mg, out);
}

// round 9
// speedup vs baseline: 1.5173x; 1.5173x over previous
#include <cuda_runtime.h>
#include <math.h>
#include <stdint.h>

#define N_PAT 4096
#define DIM   256
#define EPSV  1e-8f
#define RBLK  32                  // rows per prep block
#define NRB   (N_PAT / RBLK)      // 128 row-blocks per modality
#define NPREP (4 * NRB)           // 512 prep blocks

// ---------------- static scratch ----------------
__device__ float  g_upart[NPREP * DIM];   // [prep block][col]
__device__ float2 g_vw[NPREP];            // per (mod,rowblock) (V,W)
__device__ float  g_coxpart[N_PAT];

// ---------------- prep: row stats + weighted column partial sums ----------------
__global__ void __launch_bounds__(256)
prep_kernel(const float* __restrict__ eb0, const float* __restrict__ eb1,
            const float* __restrict__ eb2, const float* __restrict__ eb3) {
    __shared__ float smf[2048];
    __shared__ float snm[8], sww[8];

    int mod = blockIdx.x >> 7;
    int rb  = blockIdx.x & 127;
    int r0  = rb * RBLK;
    const float* base = (mod == 0) ? eb0 : (mod == 1) ? eb1
                      : (mod == 2) ? eb2 : eb3;
    int tid = threadIdx.x;
    int w = tid >> 5, lane = tid & 31;

    // 4 rows per warp, all 8 float4 loads independent (MLP = 8)
    float4 va[4], vb[4];
#pragma unroll
    for (int rr = 0; rr < 4; rr++) {
        const float4* src = (const float4*)(base + (size_t)(r0 + w * 4 + rr) * DIM);
        va[rr] = src[lane];
        vb[rr] = src[lane + 32];
    }

    float4 acc0 = make_float4(0.f, 0.f, 0.f, 0.f);
    float4 acc1 = make_float4(0.f, 0.f, 0.f, 0.f);
    float nmW = 0.0f, wW = 0.0f;
#pragma unroll
    for (int rr = 0; rr < 4; rr++) {
        float4 v0 = va[rr], v1 = vb[rr];
        float x0 = __shfl_sync(0xffffffffu, v0.x, 0);
        bool eq = (v0.x == x0) && (v0.y == x0) && (v0.z == x0) && (v0.w == x0) &&
                  (v1.x == x0) && (v1.y == x0) && (v1.z == x0) && (v1.w == x0);
        bool miss = (__ballot_sync(0xffffffffu, eq) == 0xffffffffu);

        float ss = v0.x*v0.x + v0.y*v0.y + v0.z*v0.z + v0.w*v0.w
                 + v1.x*v1.x + v1.y*v1.y + v1.z*v1.z + v1.w*v1.w;
#pragma unroll
        for (int o = 16; o > 0; o >>= 1) ss += __shfl_xor_sync(0xffffffffu, ss, o);

        float den = fmaxf(sqrtf(ss), EPSV);
        float inv = miss ? 0.0f : (1.0f / den);
        if (!miss) { nmW += 1.0f; wW += ss / (den * den); }

        acc0.x += v0.x * inv; acc0.y += v0.y * inv;
        acc0.z += v0.z * inv; acc0.w += v0.w * inv;
        acc1.x += v1.x * inv; acc1.y += v1.y * inv;
        acc1.z += v1.z * inv; acc1.w += v1.w * inv;
    }

    float* row = smf + w * 256;
    *(float4*)(row + lane * 4)       = acc0;
    *(float4*)(row + 128 + lane * 4) = acc1;
    if (lane == 0) { snm[w] = nmW; sww[w] = wW; }
    __syncthreads();

    float u = 0.0f;
#pragma unroll
    for (int ww = 0; ww < 8; ww++) u += smf[ww * 256 + tid];
    g_upart[((size_t)blockIdx.x << 8) + tid] = u;

    if (tid == 0) {
        float V = 0.0f, W = 0.0f;
#pragma unroll
        for (int i = 0; i < 8; i++) { V += snm[i]; W += sww[i]; }
        g_vw[blockIdx.x] = make_float2(V, W);
    }
}

// ---------------- cox: 16 rows per block, fused exp, tiled j ----------------
__global__ void __launch_bounds__(256)
cox_kernel(const float* __restrict__ h, const int* __restrict__ t,
           const int* __restrict__ e) {
    __shared__ int st[1024];
    __shared__ float se[1024];
    int tid = threadIdx.x;
    int il = tid >> 4;
    int sub = tid & 15;
    int i = blockIdx.x * 16 + il;
    int ti = t[i];
    float s = 0.0f;
    for (int j0 = 0; j0 < N_PAT; j0 += 1024) {
        __syncthreads();
        for (int j = tid; j < 1024; j += 256) {
            st[j] = t[j0 + j];
            se[j] = expf(h[j0 + j]);
        }
        __syncthreads();
#pragma unroll 8
        for (int j = sub; j < 1024; j += 16)
            if (ti == 0 || st[j] >= ti) s += se[j];
    }
#pragma unroll
    for (int o = 8; o > 0; o >>= 1) s += __shfl_xor_sync(0xffffffffu, s, o);
    if (sub == 0)
        g_coxpart[i] = e[i] ? (h[i] - logf(s)) : 0.0f;
}

// ---------------- finish: float4 strip-parallel reductions ----------------
__global__ void __launch_bounds__(1024)
finish_kernel(const int* __restrict__ e, const int* __restrict__ mptr,
              float* __restrict__ out) {
    __shared__ float4 sm4[1024];       // 16KB
    __shared__ float rv[1024];
    __shared__ float rw[1024];
    __shared__ float U2s[4], sV[4], sW[4];
    int tid = threadIdx.x;

    // 1) per-mod ||u||^2. thread = (mod, strip, colgroup-of-4).
    //    Each thread sums a 32-rb strip of one float4 column group (MLP=32).
    {
        int m  = tid >> 8;          // 0..3
        int s  = (tid >> 6) & 3;    // 0..3 strip
        int cg = tid & 63;          // 0..63 column group
        const float4* p = (const float4*)g_upart + ((size_t)(m * 128 + s * 32) << 6) + cg;
        float4 a = make_float4(0.f, 0.f, 0.f, 0.f);
#pragma unroll
        for (int k = 0; k < 32; k++) {
            float4 v = p[(size_t)k << 6];
            a.x += v.x; a.y += v.y; a.z += v.z; a.w += v.w;
        }
        sm4[tid] = a;
    }
    __syncthreads();
    if (tid < 256) {
        int m2 = tid >> 6, cg2 = tid & 63;
        float4 a = sm4[m2 * 256 + cg2];
        float4 b = sm4[m2 * 256 + 64 + cg2];
        float4 c = sm4[m2 * 256 + 128 + cg2];
        float4 d = sm4[m2 * 256 + 192 + cg2];
        float ux = a.x + b.x + c.x + d.x;
        float uy = a.y + b.y + c.y + d.y;
        float uz = a.z + b.z + c.z + d.z;
        float uw = a.w + b.w + c.w + d.w;
        rv[tid] = ux * ux + uy * uy + uz * uz + uw * uw;
    }
    __syncthreads();
#pragma unroll
    for (int o = 32; o > 0; o >>= 1) {
        if (tid < 256 && (tid & 63) < o) rv[tid] += rv[tid + o];
        __syncthreads();
    }
    if (tid < 4) U2s[tid] = rv[tid << 6];
    __syncthreads();

    // 2) per-mod V, W (512 entries, 128 per mod)
    {
        float V = 0.0f, W = 0.0f;
        if (tid < NPREP) { float2 vw = g_vw[tid]; V = vw.x; W = vw.y; }
        rv[tid] = V; rw[tid] = W;
    }
    __syncthreads();
#pragma unroll
    for (int o = NRB / 2; o > 0; o >>= 1) {
        if (tid < NPREP && (tid & (NRB - 1)) < o) {
            rv[tid] += rv[tid + o];
            rw[tid] += rw[tid + o];
        }
        __syncthreads();
    }
    if (tid < 4) { sV[tid] = rv[tid * NRB]; sW[tid] = rw[tid * NRB]; }
    __syncthreads();

    // 3) cox partial sum + event count
    {
        float cp = 0.0f, ef = 0.0f;
#pragma unroll
        for (int k = 0; k < N_PAT / 1024; k++) {
            int i = tid + k * 1024;
            cp += g_coxpart[i];
            ef += (float)e[i];
        }
        rv[tid] = cp; rw[tid] = ef;
    }
    __syncthreads();
#pragma unroll
    for (int o = 512; o > 0; o >>= 1) {
        if (tid < o) { rv[tid] += rv[tid + o]; rw[tid] += rw[tid + o]; }
        __syncthreads();
    }

    if (tid == 0) {
        int iv = mptr[0];
        float margin = (iv > -1000000 && iv < 1000000) ? (float)iv : __int_as_float(iv);

        double sim = (double)margin * (double)N_PAT * (double)(N_PAT - 1);
#pragma unroll
        for (int m = 0; m < 4; m++)
            sim += (double)sW[m] * (double)sV[m] - (double)U2s[m];
        double cox = -(double)rv[0] / (double)rw[0];
        out[0] = (float)(sim + cox);
    }
}

// ---------------- launch ----------------
extern "C" void kernel_launch(void* const* d_in, const int* in_sizes, int n_in,
                              void* d_out, int out_size) {
    const float* h   = (const float*)d_in[0];
    const int*   t   = (const int*)d_in[1];
    const int*   e   = (const int*)d_in[2];
    const float* eb0 = (const float*)d_in[3];
    const float* eb1 = (const float*)d_in[4];
    const float* eb2 = (const float*)d_in[5];
    const float* eb3 = (const float*)d_in[6];
    const int*   mg  = (const int*)d_in[7];
    float* out = (float*)d_out;

    prep_kernel<<<NPREP, 256>>>(eb0, eb1, eb2, eb3);
    cox_kernel<<<N_PAT / 16, 256>>>(h, t, e);
    finish_kernel<<<1, 1024>>>(e, mg, out);
}

// round 10
// speedup vs baseline: 3.3092x; 2.1810x over previous
#include <cuda_runtime.h>
#include <math.h>
#include <stdint.h>

#define N_PAT 4096
#define DIM   256
#define EPSV  1e-8f
#define RBLK  32                  // rows per prep block
#define NRB   (N_PAT / RBLK)      // 128 row-blocks per modality
#define NPREP (4 * NRB)           // 512 prep blocks
#define NBKT  4096
#define FXSCALE 1048576.0f        // 2^20 fixed-point for deterministic scatter

// ---------------- static scratch ----------------
__device__ float  g_upart[NPREP * DIM];   // [prep block][col]
__device__ float2 g_vw[NPREP];            // per (mod,rowblock) (V,W)

// ---------------- prep: row stats + weighted column partial sums ----------------
__global__ void __launch_bounds__(256)
prep_kernel(const float* __restrict__ eb0, const float* __restrict__ eb1,
            const float* __restrict__ eb2, const float* __restrict__ eb3) {
    __shared__ float smf[2048];
    __shared__ float snm[8], sww[8];

    int mod = blockIdx.x >> 7;
    int rb  = blockIdx.x & 127;
    int r0  = rb * RBLK;
    const float* base = (mod == 0) ? eb0 : (mod == 1) ? eb1
                      : (mod == 2) ? eb2 : eb3;
    int tid = threadIdx.x;
    int w = tid >> 5, lane = tid & 31;

    float4 va[4], vb[4];
#pragma unroll
    for (int rr = 0; rr < 4; rr++) {
        const float4* src = (const float4*)(base + (size_t)(r0 + w * 4 + rr) * DIM);
        va[rr] = src[lane];
        vb[rr] = src[lane + 32];
    }

    float4 acc0 = make_float4(0.f, 0.f, 0.f, 0.f);
    float4 acc1 = make_float4(0.f, 0.f, 0.f, 0.f);
    float nmW = 0.0f, wW = 0.0f;
#pragma unroll
    for (int rr = 0; rr < 4; rr++) {
        float4 v0 = va[rr], v1 = vb[rr];
        float x0 = __shfl_sync(0xffffffffu, v0.x, 0);
        bool eq = (v0.x == x0) && (v0.y == x0) && (v0.z == x0) && (v0.w == x0) &&
                  (v1.x == x0) && (v1.y == x0) && (v1.z == x0) && (v1.w == x0);
        bool miss = (__ballot_sync(0xffffffffu, eq) == 0xffffffffu);

        float ss = v0.x*v0.x + v0.y*v0.y + v0.z*v0.z + v0.w*v0.w
                 + v1.x*v1.x + v1.y*v1.y + v1.z*v1.z + v1.w*v1.w;
#pragma unroll
        for (int o = 16; o > 0; o >>= 1) ss += __shfl_xor_sync(0xffffffffu, ss, o);

        float den = fmaxf(sqrtf(ss), EPSV);
        float inv = miss ? 0.0f : (1.0f / den);
        if (!miss) { nmW += 1.0f; wW += ss / (den * den); }

        acc0.x += v0.x * inv; acc0.y += v0.y * inv;
        acc0.z += v0.z * inv; acc0.w += v0.w * inv;
        acc1.x += v1.x * inv; acc1.y += v1.y * inv;
        acc1.z += v1.z * inv; acc1.w += v1.w * inv;
    }

    float* row = smf + w * 256;
    *(float4*)(row + lane * 4)       = acc0;
    *(float4*)(row + 128 + lane * 4) = acc1;
    if (lane == 0) { snm[w] = nmW; sww[w] = wW; }
    __syncthreads();

    float u = 0.0f;
#pragma unroll
    for (int ww = 0; ww < 8; ww++) u += smf[ww * 256 + tid];
    g_upart[((size_t)blockIdx.x << 8) + tid] = u;

    if (tid == 0) {
        float V = 0.0f, W = 0.0f;
#pragma unroll
        for (int i = 0; i < 8; i++) { V += snm[i]; W += sww[i]; }
        g_vw[blockIdx.x] = make_float2(V, W);
    }
}

// ---------------- finish: cox (histogram suffix-sum) + all reductions ----------------
// dynamic smem layout:
//   [0, 32768)      u64 bkt[4096]   (first 16KB later aliased as float S[4096])
//   [32768, 49152)  float4 sm4[1024]
//   [49152, 53248)  float rv[1024]
//   [53248, 57344)  float rw[1024]
#define FIN_SMEM 57344

__global__ void __launch_bounds__(1024)
finish_kernel(const float* __restrict__ h, const int* __restrict__ t,
              const int* __restrict__ e, const int* __restrict__ mptr,
              float* __restrict__ out) {
    extern __shared__ __align__(16) char sm[];
    unsigned long long* bkt = (unsigned long long*)sm;
    float*  S   = (float*)sm;
    float4* sm4 = (float4*)(sm + 32768);
    float*  rv  = (float*)(sm + 49152);
    float*  rw  = (float*)(sm + 53248);
    __shared__ float U2s[4], sV[4], sW[4];
    int tid = threadIdx.x;

    // ---- cox phase 1: deterministic fixed-point histogram of exp(h) over t ----
#pragma unroll
    for (int k = 0; k < 4; k++) bkt[tid + k * 1024] = 0ull;
    __syncthreads();

    int   tv[4];
    float hv[4];
#pragma unroll
    for (int k = 0; k < 4; k++) {
        int i = tid + k * 1024;
        tv[k] = t[i] & (NBKT - 1);
        hv[k] = h[i];
        unsigned long long q = (unsigned long long)(expf(hv[k]) * FXSCALE);
        atomicAdd(&bkt[tv[k]], q);
    }
    __syncthreads();

    // ---- cox phase 2: suffix scan S[v] = sum_{v' >= v} bucket[v'] ----
    int base = tid * 4;
    float b0 = (float)bkt[base + 0] * (1.0f / FXSCALE);
    float b1 = (float)bkt[base + 1] * (1.0f / FXSCALE);
    float b2 = (float)bkt[base + 2] * (1.0f / FXSCALE);
    float b3 = (float)bkt[base + 3] * (1.0f / FXSCALE);
    float cs = b0 + b1 + b2 + b3;
    rv[tid] = cs;
    __syncthreads();
#pragma unroll
    for (int o = 1; o < 1024; o <<= 1) {
        float v = (tid + o < 1024) ? rv[tid + o] : 0.0f;
        __syncthreads();
        rv[tid] += v;
        __syncthreads();
    }
    float excl = rv[tid] - cs;           // sum of chunks strictly after this one
    float s3 = excl + b3;
    float s2 = s3 + b2;
    float s1 = s2 + b1;
    float s0 = s1 + b0;
    S[base + 0] = s0; S[base + 1] = s1; S[base + 2] = s2; S[base + 3] = s3;
    __syncthreads();

    // ---- cox phase 3: per-patient lookup ----
    float cp = 0.0f, ef = 0.0f;
#pragma unroll
    for (int k = 0; k < 4; k++) {
        int i = tid + k * 1024;
        int ei = e[i];
        ef += (float)ei;
        if (ei) cp += hv[k] - logf(S[tv[k]]);
    }
    __syncthreads();

    // ---- U^2: float4 strip-parallel over g_upart ----
    {
        int m  = tid >> 8;
        int s  = (tid >> 6) & 3;
        int cg = tid & 63;
        const float4* p = (const float4*)g_upart + ((size_t)(m * 128 + s * 32) << 6) + cg;
        float4 a = make_float4(0.f, 0.f, 0.f, 0.f);
#pragma unroll
        for (int k = 0; k < 32; k++) {
            float4 v = p[(size_t)k << 6];
            a.x += v.x; a.y += v.y; a.z += v.z; a.w += v.w;
        }
        sm4[tid] = a;
    }
    __syncthreads();
    if (tid < 256) {
        int m2 = tid >> 6, cg2 = tid & 63;
        float4 a = sm4[m2 * 256 + cg2];
        float4 b = sm4[m2 * 256 + 64 + cg2];
        float4 c = sm4[m2 * 256 + 128 + cg2];
        float4 d = sm4[m2 * 256 + 192 + cg2];
        float ux = a.x + b.x + c.x + d.x;
        float uy = a.y + b.y + c.y + d.y;
        float uz = a.z + b.z + c.z + d.z;
        float uw = a.w + b.w + c.w + d.w;
        rv[tid] = ux * ux + uy * uy + uz * uz + uw * uw;
    }
    __syncthreads();
#pragma unroll
    for (int o = 32; o > 0; o >>= 1) {
        if (tid < 256 && (tid & 63) < o) rv[tid] += rv[tid + o];
        __syncthreads();
    }
    if (tid < 4) U2s[tid] = rv[tid << 6];
    __syncthreads();

    // ---- per-mod V, W ----
    {
        float V = 0.0f, W = 0.0f;
        if (tid < NPREP) { float2 vw = g_vw[tid]; V = vw.x; W = vw.y; }
        rv[tid] = V; rw[tid] = W;
    }
    __syncthreads();
#pragma unroll
    for (int o = NRB / 2; o > 0; o >>= 1) {
        if (tid < NPREP && (tid & (NRB - 1)) < o) {
            rv[tid] += rv[tid + o];
            rw[tid] += rw[tid + o];
        }
        __syncthreads();
    }
    if (tid < 4) { sV[tid] = rv[tid * NRB]; sW[tid] = rw[tid * NRB]; }
    __syncthreads();

    // ---- cox reduction ----
    rv[tid] = cp; rw[tid] = ef;
    __syncthreads();
#pragma unroll
    for (int o = 512; o > 0; o >>= 1) {
        if (tid < o) { rv[tid] += rv[tid + o]; rw[tid] += rw[tid + o]; }
        __syncthreads();
    }

    if (tid == 0) {
        int iv = mptr[0];
        float margin = (iv > -1000000 && iv < 1000000) ? (float)iv : __int_as_float(iv);

        double sim = (double)margin * (double)N_PAT * (double)(N_PAT - 1);
#pragma unroll
        for (int m = 0; m < 4; m++)
            sim += (double)sW[m] * (double)sV[m] - (double)U2s[m];
        double cox = -(double)rv[0] / (double)rw[0];
        out[0] = (float)(sim + cox);
    }
}

// ---------------- launch ----------------
extern "C" void kernel_launch(void* const* d_in, const int* in_sizes, int n_in,
                              void* d_out, int out_size) {
    const float* h   = (const float*)d_in[0];
    const int*   t   = (const int*)d_in[1];
    const int*   e   = (const int*)d_in[2];
    const float* eb0 = (const float*)d_in[3];
    const float* eb1 = (const float*)d_in[4];
    const float* eb2 = (const float*)d_in[5];
    const float* eb3 = (const float*)d_in[6];
    const int*   mg  = (const int*)d_in[7];
    float* out = (float*)d_out;

    cudaFuncSetAttribute(finish_kernel, cudaFuncAttributeMaxDynamicSharedMemorySize, FIN_SMEM);

    prep_kernel<<<NPREP, 256>>>(eb0, eb1, eb2, eb3);
    finish_kernel<<<1, 1024, FIN_SMEM>>>(h, t, e, mg, out);
}

// round 11
// speedup vs baseline: 3.7124x; 1.1218x over previous
#include <cuda_runtime.h>
#include <math.h>
#include <stdint.h>

#define N_PAT 4096
#define DIM   256
#define EPSV  1e-8f
#define RBLK  32                  // rows per prep block
#define NRB   (N_PAT / RBLK)      // 128 row-blocks per modality
#define NPREP (4 * NRB)           // 512 prep blocks
#define NBKT  4096
#define FXSCALE 1048576.0f        // 2^20 fixed-point for deterministic scatter
#define NFIN  9                   // finish blocks: 0 = cox+VW, 1..8 = U^2 slices

// ---------------- static scratch ----------------
__device__ float  g_upart[NPREP * DIM];   // [prep block][col]
__device__ float2 g_vw[NPREP];            // per (mod,rowblock) (V,W)
__device__ float  g_U2part[8];            // per (mod, col-half) sum of u^2
__device__ float  g_V[4], g_W[4];         // per-mod V, W
__device__ float  g_coxsum, g_efsum;
__device__ int    g_count;                // arrival counter (reset by last block)

// ---------------- prep: row stats + weighted column partial sums ----------------
__global__ void __launch_bounds__(256)
prep_kernel(const float* __restrict__ eb0, const float* __restrict__ eb1,
            const float* __restrict__ eb2, const float* __restrict__ eb3) {
    __shared__ float smf[2048];
    __shared__ float snm[8], sww[8];

    int mod = blockIdx.x >> 7;
    int rb  = blockIdx.x & 127;
    int r0  = rb * RBLK;
    const float* base = (mod == 0) ? eb0 : (mod == 1) ? eb1
                      : (mod == 2) ? eb2 : eb3;
    int tid = threadIdx.x;
    int w = tid >> 5, lane = tid & 31;

    float4 va[4], vb[4];
#pragma unroll
    for (int rr = 0; rr < 4; rr++) {
        const float4* src = (const float4*)(base + (size_t)(r0 + w * 4 + rr) * DIM);
        va[rr] = src[lane];
        vb[rr] = src[lane + 32];
    }

    float4 acc0 = make_float4(0.f, 0.f, 0.f, 0.f);
    float4 acc1 = make_float4(0.f, 0.f, 0.f, 0.f);
    float nmW = 0.0f, wW = 0.0f;
#pragma unroll
    for (int rr = 0; rr < 4; rr++) {
        float4 v0 = va[rr], v1 = vb[rr];
        float x0 = __shfl_sync(0xffffffffu, v0.x, 0);
        bool eq = (v0.x == x0) && (v0.y == x0) && (v0.z == x0) && (v0.w == x0) &&
                  (v1.x == x0) && (v1.y == x0) && (v1.z == x0) && (v1.w == x0);
        bool miss = (__ballot_sync(0xffffffffu, eq) == 0xffffffffu);

        float ss = v0.x*v0.x + v0.y*v0.y + v0.z*v0.z + v0.w*v0.w
                 + v1.x*v1.x + v1.y*v1.y + v1.z*v1.z + v1.w*v1.w;
#pragma unroll
        for (int o = 16; o > 0; o >>= 1) ss += __shfl_xor_sync(0xffffffffu, ss, o);

        float den = fmaxf(sqrtf(ss), EPSV);
        float inv = miss ? 0.0f : (1.0f / den);
        if (!miss) { nmW += 1.0f; wW += ss / (den * den); }

        acc0.x += v0.x * inv; acc0.y += v0.y * inv;
        acc0.z += v0.z * inv; acc0.w += v0.w * inv;
        acc1.x += v1.x * inv; acc1.y += v1.y * inv;
        acc1.z += v1.z * inv; acc1.w += v1.w * inv;
    }

    float* row = smf + w * 256;
    *(float4*)(row + lane * 4)       = acc0;
    *(float4*)(row + 128 + lane * 4) = acc1;
    if (lane == 0) { snm[w] = nmW; sww[w] = wW; }
    __syncthreads();

    float u = 0.0f;
#pragma unroll
    for (int ww = 0; ww < 8; ww++) u += smf[ww * 256 + tid];
    g_upart[((size_t)blockIdx.x << 8) + tid] = u;

    if (tid == 0) {
        float V = 0.0f, W = 0.0f;
#pragma unroll
        for (int i = 0; i < 8; i++) { V += snm[i]; W += sww[i]; }
        g_vw[blockIdx.x] = make_float2(V, W);
    }
}

// ---------------- finish: 9 blocks + deterministic last-block combine ----------------
__global__ void __launch_bounds__(1024)
finish_kernel(const float* __restrict__ h, const int* __restrict__ t,
              const int* __restrict__ e, const int* __restrict__ mptr,
              float* __restrict__ out) {
    __shared__ __align__(16) unsigned long long bkt[NBKT];   // 32KB (aliased as S)
    __shared__ float rv[1024];
    __shared__ float rw[1024];
    __shared__ int s_last;
    float* S = (float*)bkt;
    int tid = threadIdx.x;
    int b = blockIdx.x;

    if (b == 0) {
        // ======== cox: fixed-point histogram + suffix scan + lookup ========
#pragma unroll
        for (int k = 0; k < 4; k++) bkt[tid + k * 1024] = 0ull;
        __syncthreads();

        int   tv[4];
        float hv[4];
#pragma unroll
        for (int k = 0; k < 4; k++) {
            int i = tid + k * 1024;
            tv[k] = t[i] & (NBKT - 1);
            hv[k] = h[i];
            unsigned long long q = (unsigned long long)(expf(hv[k]) * FXSCALE);
            atomicAdd(&bkt[tv[k]], q);
        }
        __syncthreads();

        int base = tid * 4;
        float b0 = (float)bkt[base + 0] * (1.0f / FXSCALE);
        float b1 = (float)bkt[base + 1] * (1.0f / FXSCALE);
        float b2 = (float)bkt[base + 2] * (1.0f / FXSCALE);
        float b3 = (float)bkt[base + 3] * (1.0f / FXSCALE);
        float cs = b0 + b1 + b2 + b3;
        rv[tid] = cs;
        __syncthreads();
#pragma unroll
        for (int o = 1; o < 1024; o <<= 1) {
            float v = (tid + o < 1024) ? rv[tid + o] : 0.0f;
            __syncthreads();
            rv[tid] += v;
            __syncthreads();
        }
        float excl = rv[tid] - cs;
        float s3 = excl + b3;
        float s2 = s3 + b2;
        float s1 = s2 + b1;
        float s0 = s1 + b0;
        S[base + 0] = s0; S[base + 1] = s1; S[base + 2] = s2; S[base + 3] = s3;
        __syncthreads();

        float cp = 0.0f, ef = 0.0f;
#pragma unroll
        for (int k = 0; k < 4; k++) {
            int i = tid + k * 1024;
            int ei = e[i];
            ef += (float)ei;
            if (ei) cp += hv[k] - logf(S[tv[k]]);
        }
        __syncthreads();

        // cox reduce
        rv[tid] = cp; rw[tid] = ef;
        __syncthreads();
#pragma unroll
        for (int o = 512; o > 0; o >>= 1) {
            if (tid < o) { rv[tid] += rv[tid + o]; rw[tid] += rw[tid + o]; }
            __syncthreads();
        }
        if (tid == 0) { g_coxsum = rv[0]; g_efsum = rw[0]; }

        // ======== per-mod V, W ========
        {
            float V = 0.0f, W = 0.0f;
            if (tid < NPREP) { float2 vw = g_vw[tid]; V = vw.x; W = vw.y; }
            __syncthreads();
            rv[tid] = V; rw[tid] = W;
        }
        __syncthreads();
#pragma unroll
        for (int o = NRB / 2; o > 0; o >>= 1) {
            if (tid < NPREP && (tid & (NRB - 1)) < o) {
                rv[tid] += rv[tid + o];
                rw[tid] += rw[tid + o];
            }
            __syncthreads();
        }
        if (tid < 4) { g_V[tid] = rv[tid * NRB]; g_W[tid] = rw[tid * NRB]; }
    } else {
        // ======== U^2 slice: mod = (b-1)>>1, column half = (b-1)&1 ========
        int idx  = b - 1;
        int mod  = idx >> 1;
        int half = idx & 1;
        int col  = (tid & 127) + half * 128;
        int rg   = tid >> 7;              // 0..7, each covers 16 rb
        const float* up = g_upart + (((size_t)(mod * 128 + rg * 16)) << 8) + col;
        float u = 0.0f;
#pragma unroll
        for (int k = 0; k < 16; k++) u += up[(size_t)k << 8];
        rv[tid] = u;
        __syncthreads();
        if (tid < 128) {
            float ut = 0.0f;
#pragma unroll
            for (int g = 0; g < 8; g++) ut += rv[g * 128 + tid];
            rw[tid] = ut * ut;
        }
        __syncthreads();
#pragma unroll
        for (int o = 64; o > 0; o >>= 1) {
            if (tid < o) rw[tid] += rw[tid + o];
            __syncthreads();
        }
        if (tid == 0) g_U2part[idx] = rw[0];
    }

    // ======== deterministic last-block combine ========
    __threadfence();
    if (tid == 0) {
        int c = atomicAdd(&g_count, 1);
        s_last = (c == NFIN - 1);
    }
    __syncthreads();
    if (s_last && tid == 0) {
        int iv = mptr[0];
        float margin = (iv > -1000000 && iv < 1000000) ? (float)iv : __int_as_float(iv);

        double sim = (double)margin * (double)N_PAT * (double)(N_PAT - 1);
#pragma unroll
        for (int m = 0; m < 4; m++)
            sim += (double)g_W[m] * (double)g_V[m]
                 - (double)g_U2part[2 * m] - (double)g_U2part[2 * m + 1];
        double cox = -(double)g_coxsum / (double)g_efsum;
        out[0] = (float)(sim + cox);
        g_count = 0;            // reset for next graph replay
    }
}

// ---------------- launch ----------------
extern "C" void kernel_launch(void* const* d_in, const int* in_sizes, int n_in,
                              void* d_out, int out_size) {
    const float* h   = (const float*)d_in[0];
    const int*   t   = (const int*)d_in[1];
    const int*   e   = (const int*)d_in[2];
    const float* eb0 = (const float*)d_in[3];
    const float* eb1 = (const float*)d_in[4];
    const float* eb2 = (const float*)d_in[5];
    const float* eb3 = (const float*)d_in[6];
    const int*   mg  = (const int*)d_in[7];
    float* out = (float*)d_out;

    prep_kernel<<<NPREP, 256>>>(eb0, eb1, eb2, eb3);
    finish_kernel<<<NFIN, 1024>>>(h, t, e, mg, out);
}